// round 8
// baseline (speedup 1.0000x reference)
#include <cuda_runtime.h>

#define B 8
#define T_IN 512
#define D 384
#define VPR (D / 4)          // 96 float4s per row
#define T_MEL 3584
#define MEL_MAX 2048
#define BLOCKS_PER_B 32
#define GRID (B * BLOCKS_PER_B)   // 256

__global__ void __launch_bounds__(384) fused_kernel(const float* __restrict__ enc,
                                                    const int* __restrict__ dur,
                                                    const float* __restrict__ pitch,
                                                    float* __restrict__ enc_rep,
                                                    float* __restrict__ dec_lens_out,
                                                    float* __restrict__ pitch_avg_out) {
    const int tid = threadIdx.x;
    const int lane = tid % VPR;
    const int rsub = tid / VPR;                 // 0..3
    const int b = blockIdx.x >> 5;
    const int sub = blockIdx.x & 31;
    const int t0 = sub * 16 + rsub * 4;         // this thread's 4 consecutive tokens

    // prefetch 4 enc rows — addresses are index-independent, latency hides under the scan
    const float4* encb = (const float4*)enc + ((size_t)b * T_IN + t0) * VPR + lane;
    const float4 v0 = __ldg(encb);
    const float4 v1 = __ldg(encb + VPR);
    const float4 v2 = __ldg(encb + 2 * VPR);
    const float4 v3 = __ldg(encb + 3 * VPR);

    // ---- in-block scan of this batch's 512 durations (threads 0..127, int4 each) ----
    __shared__ int cum[T_IN + 1];
    __shared__ int wsum[4];
    int s0 = 0, s1 = 0, s2 = 0, s3 = 0, pv = 0, base = 0;
    if (tid < 128) {
        int4 dv = ((const int4*)(dur + b * T_IN))[tid];
        s0 = dv.x; s1 = s0 + dv.y; s2 = s1 + dv.z; s3 = s2 + dv.w;
        pv = s3;
        const int wl = tid & 31;
        #pragma unroll
        for (int off = 1; off < 32; off <<= 1) {
            int n = __shfl_up_sync(0xffffffffu, pv, off);
            if (wl >= off) pv += n;
        }
        if (wl == 31) wsum[tid >> 5] = pv;
    }
    __syncthreads();
    if (tid < 128) {
        const int wid = tid >> 5;
        int woff = 0;
        #pragma unroll
        for (int w = 0; w < 3; w++) if (w < wid) woff += wsum[w];
        base = woff + pv - s3;                  // exclusive prefix of this int4
        cum[4 * tid + 1] = base + s0;
        cum[4 * tid + 2] = base + s1;
        cum[4 * tid + 3] = base + s2;
        cum[4 * tid + 4] = base + s3;
        if (tid == 0) cum[0] = 0;
    }
    __syncthreads();

    // ---- scatter: 4 tokens per thread, ~15 independent predicated STG.128 ----
    const int c0 = cum[t0];
    const int c1 = cum[t0 + 1];
    const int c2 = cum[t0 + 2];
    const int c3 = cum[t0 + 3];
    const int c4 = cum[t0 + 4];
    const int e1 = c1 < MEL_MAX ? c1 : MEL_MAX;
    const int e2 = c2 < MEL_MAX ? c2 : MEL_MAX;
    const int e3 = c3 < MEL_MAX ? c3 : MEL_MAX;
    const int e4 = c4 < MEL_MAX ? c4 : MEL_MAX;
    float4* outb = (float4*)enc_rep + (size_t)b * MEL_MAX * VPR + lane;
    #pragma unroll
    for (int k = 0; k < 7; k++) { int m = c0 + k; if (m < e1) outb[(size_t)m * VPR] = v0; }
    #pragma unroll
    for (int k = 0; k < 7; k++) { int m = c1 + k; if (m < e2) outb[(size_t)m * VPR] = v1; }
    #pragma unroll
    for (int k = 0; k < 7; k++) { int m = c2 + k; if (m < e3) outb[(size_t)m * VPR] = v2; }
    #pragma unroll
    for (int k = 0; k < 7; k++) { int m = c3 + k; if (m < e4) outb[(size_t)m * VPR] = v3; }

    // ---- zero-fill this block's 64-row slice where rows >= total ----
    int total = cum[T_IN];
    if (total > MEL_MAX) total = MEL_MAX;
    const int rowbase = sub * 64;
    if (rowbase + 64 > total) {
        const float4 z = make_float4(0.f, 0.f, 0.f, 0.f);
        #pragma unroll
        for (int i = 0; i < 16; i++) {
            const int m = rowbase + rsub + 4 * i;
            if (m >= total) outb[(size_t)m * VPR] = z;
        }
    }
    if (tid == 0 && sub == 0)
        dec_lens_out[b] = (float)total;

    // ---- pitch averages: threads 0..127 own tokens 4*tid..4*tid+3 via scan registers ----
    if (tid < 128) {
        const float* p = pitch + (size_t)b * T_MEL + base;
        const int d0 = s0, d1 = s1 - s0, d2 = s2 - s1, d3 = s3 - s2;
        float sm0 = 0.f, sm1 = 0.f, sm2 = 0.f, sm3 = 0.f;
        float n0 = 0.f, n1 = 0.f, n2 = 0.f, n3 = 0.f;
        #pragma unroll
        for (int k = 0; k < 7; k++) {
            if (k < d0) { float x = __ldg(p + k);       sm0 += x; if (x != 0.f) n0 += 1.f; }
            if (k < d1) { float x = __ldg(p + s0 + k);  sm1 += x; if (x != 0.f) n1 += 1.f; }
            if (k < d2) { float x = __ldg(p + s1 + k);  sm2 += x; if (x != 0.f) n2 += 1.f; }
            if (k < d3) { float x = __ldg(p + s2 + k);  sm3 += x; if (x != 0.f) n3 += 1.f; }
        }
        float* pa = pitch_avg_out + b * T_IN + 4 * tid;
        pa[0] = (n0 != 0.f) ? sm0 / n0 : 0.f;
        pa[1] = (n1 != 0.f) ? sm1 / n1 : 0.f;
        pa[2] = (n2 != 0.f) ? sm2 / n2 : 0.f;
        pa[3] = (n3 != 0.f) ? sm3 / n3 : 0.f;
    }
}

extern "C" void kernel_launch(void* const* d_in, const int* in_sizes, int n_in,
                              void* d_out, int out_size) {
    const float* enc_out = (const float*)d_in[0];   // [B, T_IN, D]
    const int* durations = (const int*)d_in[1];     // [B, T_IN]
    const float* pitch = (const float*)d_in[2];     // [B, 1, T_MEL]

    float* out = (float*)d_out;
    float* enc_rep = out;                               // B*MEL_MAX*D
    float* dec_lens = out + (size_t)B * MEL_MAX * D;    // B
    float* pitch_avg = dec_lens + B;                    // B*T_IN

    fused_kernel<<<GRID, 384>>>(enc_out, durations, pitch,
                                enc_rep, dec_lens, pitch_avg);
}

// round 9
// speedup vs baseline: 1.1373x; 1.1373x over previous
#include <cuda_runtime.h>

#define B 8
#define T_IN 512
#define D 384
#define VPR (D / 4)          // 96 float4s per row
#define T_MEL 3584
#define MEL_MAX 2048
#define ROWS_PER_BLOCK 32
#define GATHER_GRID (B * MEL_MAX / ROWS_PER_BLOCK)   // 512

// frame -> token map (-1 = zero row)
__device__ int g_idx[B * MEL_MAX];

// ---------------- prep: shuffle scan + g_idx + pitch + dec_lens ----------------
__global__ void __launch_bounds__(512) prep_kernel(const int* __restrict__ dur,
                                                   const float* __restrict__ pitch,
                                                   float* __restrict__ dec_lens_out,
                                                   float* __restrict__ pitch_avg_out) {
    const int b = blockIdx.x;
    const int tid = threadIdx.x;

    __shared__ int cum[T_IN + 1];
    __shared__ int wsum[4];

    // init g_idx to -1 (independent of scan; overlaps with it)
    int* idx = g_idx + b * MEL_MAX;
    #pragma unroll
    for (int k = 0; k < 4; k++) idx[tid + 512 * k] = -1;

    if (tid < 128) {
        int4 dv = ((const int4*)(dur + b * T_IN))[tid];
        int s0 = dv.x, s1 = s0 + dv.y, s2 = s1 + dv.z, s3 = s2 + dv.w;
        int v = s3;
        const int wl = tid & 31;
        #pragma unroll
        for (int off = 1; off < 32; off <<= 1) {
            int n = __shfl_up_sync(0xffffffffu, v, off);
            if (wl >= off) v += n;
        }
        if (wl == 31) wsum[tid >> 5] = v;
        cum[4 * tid + 1] = v - s3 + s0;
        cum[4 * tid + 2] = v - s3 + s1;
        cum[4 * tid + 3] = v - s3 + s2;
        cum[4 * tid + 4] = v;
        if (tid == 0) cum[0] = 0;
    }
    __syncthreads();
    if (tid < 128) {
        const int wid = tid >> 5;
        int woff = 0;
        #pragma unroll
        for (int w = 0; w < 3; w++) if (w < wid) woff += wsum[w];
        if (woff) {
            cum[4 * tid + 1] += woff;
            cum[4 * tid + 2] += woff;
            cum[4 * tid + 3] += woff;
            cum[4 * tid + 4] += woff;
        }
    }
    __syncthreads();

    const int start = cum[tid];
    const int end = cum[tid + 1];

    if (tid == 0) {
        int total = cum[T_IN];
        dec_lens_out[b] = (float)(total < MEL_MAX ? total : MEL_MAX);
    }

    // g_idx range fill: ≤7 predicated independent stores
    const int e = end < MEL_MAX ? end : MEL_MAX;
    #pragma unroll
    for (int k = 0; k < 7; k++) {
        const int m = start + k;
        if (m < e) idx[m] = tid;
    }

    // pitch average: ≤7 predicated independent loads (N_FORMANTS = 1)
    {
        const float* p = pitch + (size_t)b * T_MEL;
        float s = 0.0f, cnt = 0.0f;
        #pragma unroll
        for (int k = 0; k < 7; k++) {
            const int m = start + k;
            if (m < end) {
                float x = __ldg(&p[m]);
                s += x;
                if (x != 0.0f) cnt += 1.0f;
            }
        }
        pitch_avg_out[b * T_IN + tid] = (cnt != 0.0f) ? (s / cnt) : 0.0f;
    }
}

// ---------------- gather: 8 independent rows per thread, single-wave grid ----------------
// block = 384 threads = 4 row-groups x 96 lanes; block covers 32 rows (stride 4).
__global__ void __launch_bounds__(384) gather_kernel(const float* __restrict__ enc,
                                                     float* __restrict__ out) {
    const int lane = threadIdx.x % VPR;
    const int rsub = threadIdx.x / VPR;              // 0..3
    const int row0 = blockIdx.x * ROWS_PER_BLOCK + rsub;
    const int b = blockIdx.x >> 6;                   // 64 blocks per batch

    // phase 1: 8 independent idx loads
    int t[8];
    #pragma unroll
    for (int k = 0; k < 8; k++) t[k] = __ldg(&g_idx[row0 + 4 * k]);

    // phase 2: 8 independent gathers
    const float4* encb = (const float4*)enc + (size_t)b * T_IN * VPR + lane;
    float4 v[8];
    #pragma unroll
    for (int k = 0; k < 8; k++) {
        v[k] = (t[k] >= 0) ? __ldg(encb + (size_t)t[k] * VPR)
                           : make_float4(0.f, 0.f, 0.f, 0.f);
    }

    // phase 3: 8 coalesced independent stores
    float4* outp = (float4*)out + (size_t)row0 * VPR + lane;
    #pragma unroll
    for (int k = 0; k < 8; k++) outp[(size_t)(4 * k) * VPR] = v[k];
}

extern "C" void kernel_launch(void* const* d_in, const int* in_sizes, int n_in,
                              void* d_out, int out_size) {
    const float* enc_out = (const float*)d_in[0];   // [B, T_IN, D]
    const int* durations = (const int*)d_in[1];     // [B, T_IN]
    const float* pitch = (const float*)d_in[2];     // [B, 1, T_MEL]

    float* out = (float*)d_out;
    float* enc_rep = out;                               // B*MEL_MAX*D
    float* dec_lens = out + (size_t)B * MEL_MAX * D;    // B
    float* pitch_avg = dec_lens + B;                    // B*T_IN

    prep_kernel<<<B, 512>>>(durations, pitch, dec_lens, pitch_avg);
    gather_kernel<<<GATHER_GRID, 384>>>(enc_out, enc_rep);
}